// round 13
// baseline (speedup 1.0000x reference)
#include <cuda_runtime.h>
#include <cuda_fp16.h>
#include <cstdint>

#define B_ 256
#define T_ 512
#define R_ 2048
#define O_ 10

#define KCH_B 4096                 // bytes of one k32 A-or-B sub-chunk (fragment order)
#define STAGE_B (2*KCH_B)          // A + B = 8 KB
#define NGROUP 6
#define SMEM_BYTES (3*NGROUP*STAGE_B)   // 3 stages x 6 groups = 144 KB

// ---------------- device scratch ----------------
__device__ __align__(128) float    g_H[2][B_ * R_];              // fp32 state
__device__ __align__(128) uint32_t g_Hh[2][4 * 32 * 2048];       // fp16 A operand, fragment order
__device__ __align__(128) uint32_t g_Xh[T_ * 4 * 2048];          // fp16 x chunks, fragment order
__device__ __align__(128) uint32_t g_Wh[32 * 33 * 2048];         // fp16 B operand, fragment order
__device__ uint32_t g_ready[4][32];                               // producer step flags
__device__ uint32_t g_cons[4][32];                                // consumer step flags
__device__ uint32_t g_always = 0xFFFFFFFFu;                       // "always ready"

__device__ __forceinline__ void cp16(void* dst, const void* src) {
    uint32_t d = (uint32_t)__cvta_generic_to_shared(dst);
    asm volatile("cp.async.cg.shared.global [%0], [%1], 16;\n" :: "r"(d), "l"(src));
}
__device__ __forceinline__ float tanh_fast(float x) {
    float r; asm("tanh.approx.f32 %0, %1;" : "=f"(r) : "f"(x)); return r;
}
__device__ __forceinline__ uint32_t ld_acq(const uint32_t* p) {
    uint32_t v;
    asm volatile("ld.acquire.gpu.global.u32 %0, [%1];" : "=r"(v) : "l"(p) : "memory");
    return v;
}
__device__ __forceinline__ void st_rel(uint32_t* p, uint32_t v) {
    asm volatile("st.release.gpu.global.u32 [%0], %1;" :: "l"(p), "r"(v) : "memory");
}

#define MMA(cc, av, bb0, bb1) \
    asm volatile("mma.sync.aligned.m16n8k16.row.col.f32.f16.f16.f32 " \
        "{%0,%1,%2,%3},{%4,%5,%6,%7},{%8,%9},{%0,%1,%2,%3};\n" \
        : "+f"((cc)[0]), "+f"((cc)[1]), "+f"((cc)[2]), "+f"((cc)[3]) \
        : "r"((av).x), "r"((av).y), "r"((av).z), "r"((av).w), "r"(bb0), "r"(bb1))

// ---------------- prep: permute + fp16-round operands once ----------------
__global__ void prep_W(const float* __restrict__ Wres, const float* __restrict__ Win) {
    uint32_t idx = blockIdx.x * 256u + threadIdx.x;      // 1056*2048 k-pairs
    uint32_t k2 = idx >> 11, n = idx & 2047u;
    uint32_t k = k2 * 2u;
    float v0, v1;
    if (k < 2048u) { v0 = Wres[(size_t)k * R_ + n]; v1 = Wres[(size_t)(k + 1) * R_ + n]; }
    else           { v0 = Win[(size_t)(k - 2048u) * R_ + n]; v1 = Win[(size_t)(k - 2047u) * R_ + n]; }
    uint32_t kc = k >> 6, kl = k & 63u;
    uint32_t k16 = kl >> 4, kin = kl & 15u, khalf = kin >> 3, tg = (kin & 7u) >> 1;
    uint32_t g = n & 7u, ni = (n >> 3) & 3u, nh = (n >> 5) & 1u, bn = n >> 6;
    uint32_t lane = g * 4u + tg;
    __half2 h = __floats2half2_rn(v0, v1);
    g_Wh[(bn * 33u + kc) * 2048u + ((k16 * 2u + nh) * 32u + lane) * 8u
         + (ni >> 1) * 4u + (ni & 1u) * 2u + khalf] = *(uint32_t*)&h;
}

__global__ void prep_X(const float* __restrict__ x) {
    uint32_t idx = blockIdx.x * 256u + threadIdx.x;      // 256*512*32 i-pairs
    uint32_t b = idx >> 14, t = (idx >> 5) & 511u, i = (idx & 31u) * 2u;
    float2 v = *(const float2*)(x + ((size_t)b * T_ + t) * 64u + i);
    uint32_t k16 = i >> 4, kin = i & 15u, khalf = kin >> 3, tg = (kin & 7u) >> 1;
    uint32_t g = b & 7u, rhi = (b >> 3) & 1u, mi = (b >> 4) & 1u, mh = (b >> 5) & 1u, bm = b >> 6;
    uint32_t lane = g * 4u + tg;
    __half2 h = __floats2half2_rn(v.x, v.y);
    g_Xh[(t * 4u + bm) * 2048u + ((k16 * 4u + mh * 2u + mi) * 32u + lane) * 4u
         + rhi + 2u * khalf] = *(uint32_t*)&h;
}

__global__ void esn_zero() {
    uint32_t i = blockIdx.x * 256u + threadIdx.x;        // 131072
    ((float4*)g_H[0])[i] = make_float4(0.f, 0.f, 0.f, 0.f);
    if (i < 65536u) ((uint4*)g_Hh[0])[i] = make_uint4(0u, 0u, 0u, 0u);
    if (i < 128u) { (&g_ready[0][0])[i] = 0u; (&g_cons[0][0])[i] = 0u; }
}

// ---------------- persistent dataflow scan ----------------
// 384 threads = 6 warp-groups of 2 warps; group g: k32 tiles kt = 6j+g, j=0..10.
// One launch runs all T_ steps. No grid barrier: per-tile ready/cons flags.
__global__ __launch_bounds__(384, 1) void esn_steps()
{
    extern __shared__ char smem[];
    const int tid = threadIdx.x;
    const int gid = tid >> 6, gtid = tid & 63;           // 6 groups of 64 threads
    const int warp = gtid >> 5, lane = gtid & 31;        // warp = n-half (0/1)
    const int bn = blockIdx.x, bm = blockIdx.y;
    char* gsm = smem + gid * 3 * STAGE_B;
    const int NCH = 11;

    auto flagAddr = [&](int j) -> const uint32_t* {
        const int kt = 6 * j + gid;
        return (kt < 64) ? &g_ready[bm][kt >> 1] : &g_always;
    };

    for (int t = 0; t < T_; t++) {
        const int cur = t & 1, nxt = cur ^ 1;
        const uint32_t tgt = (uint32_t)t;

        __align__(16) float c[4][4][4];
#pragma unroll
        for (int mi = 0; mi < 4; mi++)
#pragma unroll
            for (int nq = 0; nq < 4; nq++)
#pragma unroll
                for (int i = 0; i < 4; i++) c[mi][nq][i] = 0.f;

        auto issue = [&](int j) {
            const int kt = 6 * j + gid;                  // k32 tile 0..65
            char* dst = gsm + (j % 3) * STAGE_B;
            const uint32_t* a = (kt < 64)
                ? (g_Hh[cur] + (size_t)(bm * 32 + (kt >> 1)) * 2048 + (kt & 1) * 1024)
                : (g_Xh + (size_t)(t * 4 + bm) * 2048 + (kt & 1) * 1024);
            const uint32_t* b = g_Wh + (size_t)(bn * 33 + (kt >> 1)) * 2048 + (kt & 1) * 1024;
#pragma unroll
            for (int it = 0; it < 4; it++) { int e = (it * 64 + gtid) * 4; cp16(dst + e * 4, a + e); }
#pragma unroll
            for (int it = 0; it < 4; it++) { int e = (it * 64 + gtid) * 4; cp16(dst + KCH_B + e * 4, b + e); }
            asm volatile("cp.async.commit_group;\n" ::);
        };

        // blocking waits for the first two chunks (their producers just finished step t-1)
        { const uint32_t* f0 = flagAddr(0); while (ld_acq(f0) < tgt) {} }
        issue(0);
        { const uint32_t* f1 = flagAddr(1); while (ld_acq(f1) < tgt) {} }
        issue(1);
        uint32_t fv = ld_acq(flagAddr(2));               // prefetch flag for chunk 2

        for (int j = 0; j < NCH; j++) {
            if (j < NCH - 1) asm volatile("cp.async.wait_group 1;\n" ::);
            else             asm volatile("cp.async.wait_group 0;\n" ::);
            asm volatile("bar.sync %0, 64;" :: "r"(gid + 1) : "memory");
            if (j + 2 < NCH) {
                const uint32_t* fj = flagAddr(j + 2);
                while (fv < tgt) fv = ld_acq(fj);
                issue(j + 2);
                if (j + 3 < NCH) fv = ld_acq(flagAddr(j + 3));
            }

            const uint4* sA = (const uint4*)(gsm + (j % 3) * STAGE_B);
            const uint4* sB = (const uint4*)(gsm + (j % 3) * STAGE_B + KCH_B);

            uint4 fa[2][4], fb[2][2];
#pragma unroll
            for (int q = 0; q < 4; q++) fa[0][q] = sA[q * 32 + lane];
            fb[0][0] = sB[(warp * 32 + lane) * 2];
            fb[0][1] = sB[(warp * 32 + lane) * 2 + 1];
#pragma unroll
            for (int kl = 0; kl < 2; kl++) {
                if (kl == 0) {
#pragma unroll
                    for (int q = 0; q < 4; q++) fa[1][q] = sA[(4 + q) * 32 + lane];
                    fb[1][0] = sB[((2 + warp) * 32 + lane) * 2];
                    fb[1][1] = sB[((2 + warp) * 32 + lane) * 2 + 1];
                }
                MMA(c[0][0], fa[kl][0], fb[kl][0].x, fb[kl][0].y);
                MMA(c[0][1], fa[kl][0], fb[kl][0].z, fb[kl][0].w);
                MMA(c[0][2], fa[kl][0], fb[kl][1].x, fb[kl][1].y);
                MMA(c[0][3], fa[kl][0], fb[kl][1].z, fb[kl][1].w);
                MMA(c[1][0], fa[kl][1], fb[kl][0].x, fb[kl][0].y);
                MMA(c[1][1], fa[kl][1], fb[kl][0].z, fb[kl][0].w);
                MMA(c[1][2], fa[kl][1], fb[kl][1].x, fb[kl][1].y);
                MMA(c[1][3], fa[kl][1], fb[kl][1].z, fb[kl][1].w);
                MMA(c[2][0], fa[kl][2], fb[kl][0].x, fb[kl][0].y);
                MMA(c[2][1], fa[kl][2], fb[kl][0].z, fb[kl][0].w);
                MMA(c[2][2], fa[kl][2], fb[kl][1].x, fb[kl][1].y);
                MMA(c[2][3], fa[kl][2], fb[kl][1].z, fb[kl][1].w);
                MMA(c[3][0], fa[kl][3], fb[kl][0].x, fb[kl][0].y);
                MMA(c[3][1], fa[kl][3], fb[kl][0].z, fb[kl][0].w);
                MMA(c[3][2], fa[kl][3], fb[kl][1].x, fb[kl][1].y);
                MMA(c[3][3], fa[kl][3], fb[kl][1].z, fb[kl][1].w);
            }
        }

        // -------- signal consumption, combine partials, guarded epilogue --------
        __syncthreads();                                 // all groups' loads complete
        if (tid == 0) st_rel(&g_cons[bm][bn], (uint32_t)(t + 1));

        float4* part = (float4*)smem;
#pragma unroll
        for (int mi = 0; mi < 4; mi++)
#pragma unroll
            for (int nq = 0; nq < 4; nq++) {
                const int f = mi * 4 + nq;
                part[((f * 2 + warp) * 6 + gid) * 32 + lane] = *(const float4*)c[mi][nq];
            }
        // WAW guard: all consumers must have finished reading the buffer we overwrite
        if (tid < 32) { while (ld_acq(&g_cons[bm][tid]) < tgt) {} }
        __syncthreads();

        for (int s = tid; s < 1024; s += 384) {
            const int fp = s >> 6, w = (s >> 5) & 1, ln = s & 31;
            const int gg = ln >> 2, tgg = ln & 3;
            const float4* p = part + ((fp * 2 + w) * 6) * 32 + ln;
            float4 s0 = p[0 * 32], s1 = p[1 * 32], s2 = p[2 * 32];
            float4 s3 = p[3 * 32], s4 = p[4 * 32], s5 = p[5 * 32];
            float v[4];
            v[0] = ((s0.x + s1.x) + (s2.x + s3.x)) + (s4.x + s5.x);
            v[1] = ((s0.y + s1.y) + (s2.y + s3.y)) + (s4.y + s5.y);
            v[2] = ((s0.z + s1.z) + (s2.z + s3.z)) + (s4.z + s5.z);
            v[3] = ((s0.w + s1.w) + (s2.w + s3.w)) + (s4.w + s5.w);

            const int mi = fp >> 2, nq = fp & 3;
            const int col = bn * 64 + w * 32 + nq * 8 + tgg * 2;
#pragma unroll
            for (int rhi = 0; rhi < 2; rhi++) {
                const int row = bm * 64 + mi * 16 + rhi * 8 + gg;
                const float2 ho = *(const float2*)(g_H[cur] + (size_t)row * R_ + col);
                float h0 = 0.5f * ho.x + 0.5f * tanh_fast(v[2 * rhi]);
                float h1 = 0.5f * ho.y + 0.5f * tanh_fast(v[2 * rhi + 1]);
                *(float2*)(g_H[nxt] + (size_t)row * R_ + col) = make_float2(h0, h1);
                __half2 hh = __floats2half2_rn(h0, h1);
                const uint32_t off = (uint32_t)(bm * 32 + bn) * 2048u
                    + (uint32_t)((w * 2 + (nq >> 1)) * 4 + (mi >> 1) * 2 + (mi & 1)) * 128u
                    + (uint32_t)ln * 4u + (uint32_t)(rhi + 2 * (nq & 1));
                g_Hh[nxt][off] = *(uint32_t*)&hh;
            }
        }

        __threadfence();                                 // publish Hh writes
        __syncthreads();
        if (tid == 0) st_rel(&g_ready[bm][bn], (uint32_t)(t + 1));
    }
}

// ---------------- readout ----------------
__global__ void esn_readout(const float* __restrict__ W_out,
                            const float* __restrict__ b_out,
                            float* __restrict__ out)
{
    int b = blockIdx.x, tid = threadIdx.x;
    const float* h = g_H[0] + (size_t)b * R_;
    float acc[O_];
#pragma unroll
    for (int o = 0; o < O_; o++) acc[o] = 0.f;
    for (int r = tid; r < R_; r += 256) {
        float hv = h[r];
#pragma unroll
        for (int o = 0; o < O_; o++) acc[o] += hv * W_out[r * O_ + o];
    }
#pragma unroll
    for (int o = 0; o < O_; o++)
#pragma unroll
        for (int off = 16; off > 0; off >>= 1)
            acc[o] += __shfl_down_sync(0xffffffffu, acc[o], off);
    __shared__ float s[8][O_];
    if ((tid & 31) == 0)
#pragma unroll
        for (int o = 0; o < O_; o++) s[tid >> 5][o] = acc[o];
    __syncthreads();
    if (tid < O_) {
        float v = b_out[tid];
#pragma unroll
        for (int w = 0; w < 8; w++) v += s[w][tid];
        out[b * O_ + tid] = v;
    }
}

extern "C" void kernel_launch(void* const* d_in, const int* in_sizes, int n_in,
                              void* d_out, int out_size)
{
    const float* x     = (const float*)d_in[0];
    const float* W_in  = (const float*)d_in[1];
    const float* W_res = (const float*)d_in[2];
    const float* W_out = (const float*)d_in[3];
    const float* b_out = (const float*)d_in[4];
    float* out = (float*)d_out;

    cudaFuncSetAttribute(esn_steps, cudaFuncAttributeMaxDynamicSharedMemorySize, SMEM_BYTES);

    prep_W<<<(1056 * 2048) / 256, 256>>>(W_res, W_in);
    prep_X<<<(B_ * T_ * 32) / 256, 256>>>(x);
    esn_zero<<<512, 256>>>();

    dim3 grid(32, 4);   // 128 CTAs, 1/SM, all co-resident -> dataflow flags safe
    esn_steps<<<grid, 384, SMEM_BYTES>>>();

    esn_readout<<<B_, 256>>>(W_out, b_out, out);
}

// round 14
// speedup vs baseline: 1.1387x; 1.1387x over previous
#include <cuda_runtime.h>
#include <cuda_fp16.h>
#include <cstdint>

#define B_ 256
#define T_ 512
#define R_ 2048
#define O_ 10

#define KCH_B 4096                 // bytes of one k32 A-or-B sub-chunk (fragment order)
#define STAGE_B (2*KCH_B)          // A + B = 8 KB
#define NGROUP 6
#define SMEM_BYTES (3*NGROUP*STAGE_B)   // 3 stages x 6 groups = 144 KB

// ---------------- device scratch ----------------
__device__ __align__(128) float    g_H[2][B_ * R_];              // fp32 state (ping-pong)
__device__ __align__(128) uint32_t g_Hh[2][4 * 32 * 2048];       // fp16 A operand, fragment order
__device__ __align__(128) uint32_t g_Xh[T_ * 4 * 2048];          // fp16 x chunks, fragment order
__device__ __align__(128) uint32_t g_Wh[32 * 33 * 2048];         // fp16 B operand, fragment order
__device__ uint32_t g_ready[4][32];                               // producer step flags
__device__ uint32_t g_always = 0xFFFFFFFFu;                       // "always ready"

__device__ __forceinline__ void cp16(void* dst, const void* src) {
    uint32_t d = (uint32_t)__cvta_generic_to_shared(dst);
    asm volatile("cp.async.cg.shared.global [%0], [%1], 16;\n" :: "r"(d), "l"(src));
}
__device__ __forceinline__ float tanh_fast(float x) {
    float r; asm("tanh.approx.f32 %0, %1;" : "=f"(r) : "f"(x)); return r;
}
__device__ __forceinline__ uint32_t ld_acq(const uint32_t* p) {
    uint32_t v;
    asm volatile("ld.acquire.gpu.global.u32 %0, [%1];" : "=r"(v) : "l"(p) : "memory");
    return v;
}
__device__ __forceinline__ void st_rel(uint32_t* p, uint32_t v) {
    asm volatile("st.release.gpu.global.u32 [%0], %1;" :: "l"(p), "r"(v) : "memory");
}

#define MMA(cc, av, bb0, bb1) \
    asm volatile("mma.sync.aligned.m16n8k16.row.col.f32.f16.f16.f32 " \
        "{%0,%1,%2,%3},{%4,%5,%6,%7},{%8,%9},{%0,%1,%2,%3};\n" \
        : "+f"((cc)[0]), "+f"((cc)[1]), "+f"((cc)[2]), "+f"((cc)[3]) \
        : "r"((av).x), "r"((av).y), "r"((av).z), "r"((av).w), "r"(bb0), "r"(bb1))

// ---------------- prep: permute + fp16-round operands once ----------------
__global__ void prep_W(const float* __restrict__ Wres, const float* __restrict__ Win) {
    uint32_t idx = blockIdx.x * 256u + threadIdx.x;      // 1056*2048 k-pairs
    uint32_t k2 = idx >> 11, n = idx & 2047u;
    uint32_t k = k2 * 2u;
    float v0, v1;
    if (k < 2048u) { v0 = Wres[(size_t)k * R_ + n]; v1 = Wres[(size_t)(k + 1) * R_ + n]; }
    else           { v0 = Win[(size_t)(k - 2048u) * R_ + n]; v1 = Win[(size_t)(k - 2047u) * R_ + n]; }
    uint32_t kc = k >> 6, kl = k & 63u;
    uint32_t k16 = kl >> 4, kin = kl & 15u, khalf = kin >> 3, tg = (kin & 7u) >> 1;
    uint32_t g = n & 7u, ni = (n >> 3) & 3u, nh = (n >> 5) & 1u, bn = n >> 6;
    uint32_t lane = g * 4u + tg;
    __half2 h = __floats2half2_rn(v0, v1);
    g_Wh[(bn * 33u + kc) * 2048u + ((k16 * 2u + nh) * 32u + lane) * 8u
         + (ni >> 1) * 4u + (ni & 1u) * 2u + khalf] = *(uint32_t*)&h;
}

__global__ void prep_X(const float* __restrict__ x) {
    uint32_t idx = blockIdx.x * 256u + threadIdx.x;      // 256*512*32 i-pairs
    uint32_t b = idx >> 14, t = (idx >> 5) & 511u, i = (idx & 31u) * 2u;
    float2 v = *(const float2*)(x + ((size_t)b * T_ + t) * 64u + i);
    uint32_t k16 = i >> 4, kin = i & 15u, khalf = kin >> 3, tg = (kin & 7u) >> 1;
    uint32_t g = b & 7u, rhi = (b >> 3) & 1u, mi = (b >> 4) & 1u, mh = (b >> 5) & 1u, bm = b >> 6;
    uint32_t lane = g * 4u + tg;
    __half2 h = __floats2half2_rn(v.x, v.y);
    g_Xh[(t * 4u + bm) * 2048u + ((k16 * 4u + mh * 2u + mi) * 32u + lane) * 4u
         + rhi + 2u * khalf] = *(uint32_t*)&h;
}

__global__ void esn_zero() {
    uint32_t i = blockIdx.x * 256u + threadIdx.x;        // 131072
    ((float4*)g_H[0])[i] = make_float4(0.f, 0.f, 0.f, 0.f);
    if (i < 65536u) ((uint4*)g_Hh[0])[i] = make_uint4(0u, 0u, 0u, 0u);
    if (i < 128u) (&g_ready[0][0])[i] = 0u;
}

// ---------------- persistent dataflow scan ----------------
// 384 threads = 6 warp-groups of 2 warps; group g: k32 tiles kt = 6j+g, j=0..10.
// One launch runs all T_ steps. RAW sync via per-tile ready flags, polled by ONE
// thread per group and published to the group by the existing per-chunk barrier.
// No WAW guard needed: producer epilogue at step t implies all row flags >= t,
// so ping-pong buffers never collide (writer (t+1)&1, oldest reader t&1).
__global__ __launch_bounds__(384, 1) void esn_steps()
{
    extern __shared__ char smem[];
    const int tid = threadIdx.x;
    const int gid = tid >> 6, gtid = tid & 63;           // 6 groups of 64 threads
    const int warp = gtid >> 5, lane = gtid & 31;        // warp = n-half (0/1)
    const int bn = blockIdx.x, bm = blockIdx.y;
    char* gsm = smem + gid * 3 * STAGE_B;
    const int NCH = 11;

    auto flagAddr = [&](int j) -> const uint32_t* {
        const int kt = 6 * j + gid;
        return (kt < 64) ? &g_ready[bm][kt >> 1] : &g_always;
    };

    for (int t = 0; t < T_; t++) {
        const int cur = t & 1, nxt = cur ^ 1;
        const uint32_t tgt = (uint32_t)t;

        __align__(16) float c[4][4][4];
#pragma unroll
        for (int mi = 0; mi < 4; mi++)
#pragma unroll
            for (int nq = 0; nq < 4; nq++)
#pragma unroll
                for (int i = 0; i < 4; i++) c[mi][nq][i] = 0.f;

        auto issue = [&](int j) {
            const int kt = 6 * j + gid;                  // k32 tile 0..65
            char* dst = gsm + (j % 3) * STAGE_B;
            const uint32_t* a = (kt < 64)
                ? (g_Hh[cur] + (size_t)(bm * 32 + (kt >> 1)) * 2048 + (kt & 1) * 1024)
                : (g_Xh + (size_t)(t * 4 + bm) * 2048 + (kt & 1) * 1024);
            const uint32_t* b = g_Wh + (size_t)(bn * 33 + (kt >> 1)) * 2048 + (kt & 1) * 1024;
#pragma unroll
            for (int it = 0; it < 4; it++) { int e = (it * 64 + gtid) * 4; cp16(dst + e * 4, a + e); }
#pragma unroll
            for (int it = 0; it < 4; it++) { int e = (it * 64 + gtid) * 4; cp16(dst + KCH_B + e * 4, b + e); }
            asm volatile("cp.async.commit_group;\n" ::);
        };

        // single-thread poll for chunks 0,1; group barrier hands off to issuers
        if (gtid == 0) {
            const uint32_t* f0 = flagAddr(0);
            while (ld_acq(f0) < tgt) {}
            const uint32_t* f1 = flagAddr(1);
            while (ld_acq(f1) < tgt) {}
        }
        asm volatile("bar.sync %0, 64;" :: "r"(gid + 1) : "memory");
        issue(0); issue(1);

        for (int j = 0; j < NCH; j++) {
            if (j < NCH - 1) asm volatile("cp.async.wait_group 1;\n" ::);
            else             asm volatile("cp.async.wait_group 0;\n" ::);
            if (gtid == 0 && j + 2 < NCH) {
                const uint32_t* fj = flagAddr(j + 2);
                while (ld_acq(fj) < tgt) {}
            }
            asm volatile("bar.sync %0, 64;" :: "r"(gid + 1) : "memory");
            if (j + 2 < NCH) issue(j + 2);

            const uint4* sA = (const uint4*)(gsm + (j % 3) * STAGE_B);
            const uint4* sB = (const uint4*)(gsm + (j % 3) * STAGE_B + KCH_B);

            uint4 fa[2][4], fb[2][2];
#pragma unroll
            for (int q = 0; q < 4; q++) fa[0][q] = sA[q * 32 + lane];
            fb[0][0] = sB[(warp * 32 + lane) * 2];
            fb[0][1] = sB[(warp * 32 + lane) * 2 + 1];
#pragma unroll
            for (int kl = 0; kl < 2; kl++) {
                if (kl == 0) {
#pragma unroll
                    for (int q = 0; q < 4; q++) fa[1][q] = sA[(4 + q) * 32 + lane];
                    fb[1][0] = sB[((2 + warp) * 32 + lane) * 2];
                    fb[1][1] = sB[((2 + warp) * 32 + lane) * 2 + 1];
                }
                MMA(c[0][0], fa[kl][0], fb[kl][0].x, fb[kl][0].y);
                MMA(c[0][1], fa[kl][0], fb[kl][0].z, fb[kl][0].w);
                MMA(c[0][2], fa[kl][0], fb[kl][1].x, fb[kl][1].y);
                MMA(c[0][3], fa[kl][0], fb[kl][1].z, fb[kl][1].w);
                MMA(c[1][0], fa[kl][1], fb[kl][0].x, fb[kl][0].y);
                MMA(c[1][1], fa[kl][1], fb[kl][0].z, fb[kl][0].w);
                MMA(c[1][2], fa[kl][1], fb[kl][1].x, fb[kl][1].y);
                MMA(c[1][3], fa[kl][1], fb[kl][1].z, fb[kl][1].w);
                MMA(c[2][0], fa[kl][2], fb[kl][0].x, fb[kl][0].y);
                MMA(c[2][1], fa[kl][2], fb[kl][0].z, fb[kl][0].w);
                MMA(c[2][2], fa[kl][2], fb[kl][1].x, fb[kl][1].y);
                MMA(c[2][3], fa[kl][2], fb[kl][1].z, fb[kl][1].w);
                MMA(c[3][0], fa[kl][3], fb[kl][0].x, fb[kl][0].y);
                MMA(c[3][1], fa[kl][3], fb[kl][0].z, fb[kl][0].w);
                MMA(c[3][2], fa[kl][3], fb[kl][1].x, fb[kl][1].y);
                MMA(c[3][3], fa[kl][3], fb[kl][1].z, fb[kl][1].w);
            }
        }

        // -------- combine 6 split-K partials + epilogue (identical to R12) --------
        __syncthreads();
        float4* part = (float4*)smem;
#pragma unroll
        for (int mi = 0; mi < 4; mi++)
#pragma unroll
            for (int nq = 0; nq < 4; nq++) {
                const int f = mi * 4 + nq;
                part[((f * 2 + warp) * 6 + gid) * 32 + lane] = *(const float4*)c[mi][nq];
            }
        __syncthreads();

        for (int s = tid; s < 1024; s += 384) {
            const int fp = s >> 6, w = (s >> 5) & 1, ln = s & 31;
            const int gg = ln >> 2, tgg = ln & 3;
            const float4* p = part + ((fp * 2 + w) * 6) * 32 + ln;
            float4 s0 = p[0 * 32], s1 = p[1 * 32], s2 = p[2 * 32];
            float4 s3 = p[3 * 32], s4 = p[4 * 32], s5 = p[5 * 32];
            float v[4];
            v[0] = ((s0.x + s1.x) + (s2.x + s3.x)) + (s4.x + s5.x);
            v[1] = ((s0.y + s1.y) + (s2.y + s3.y)) + (s4.y + s5.y);
            v[2] = ((s0.z + s1.z) + (s2.z + s3.z)) + (s4.z + s5.z);
            v[3] = ((s0.w + s1.w) + (s2.w + s3.w)) + (s4.w + s5.w);

            const int mi = fp >> 2, nq = fp & 3;
            const int col = bn * 64 + w * 32 + nq * 8 + tgg * 2;
#pragma unroll
            for (int rhi = 0; rhi < 2; rhi++) {
                const int row = bm * 64 + mi * 16 + rhi * 8 + gg;
                const float2 ho = *(const float2*)(g_H[cur] + (size_t)row * R_ + col);
                float h0 = 0.5f * ho.x + 0.5f * tanh_fast(v[2 * rhi]);
                float h1 = 0.5f * ho.y + 0.5f * tanh_fast(v[2 * rhi + 1]);
                *(float2*)(g_H[nxt] + (size_t)row * R_ + col) = make_float2(h0, h1);
                __half2 hh = __floats2half2_rn(h0, h1);
                const uint32_t off = (uint32_t)(bm * 32 + bn) * 2048u
                    + (uint32_t)((w * 2 + (nq >> 1)) * 4 + (mi >> 1) * 2 + (mi & 1)) * 128u
                    + (uint32_t)ln * 4u + (uint32_t)(rhi + 2 * (nq & 1));
                g_Hh[nxt][off] = *(uint32_t*)&hh;
            }
        }

        __threadfence();                                 // publish Hh writes (gpu scope)
        __syncthreads();
        if (tid == 0) st_rel(&g_ready[bm][bn], (uint32_t)(t + 1));
    }
}

// ---------------- readout ----------------
__global__ void esn_readout(const float* __restrict__ W_out,
                            const float* __restrict__ b_out,
                            float* __restrict__ out)
{
    int b = blockIdx.x, tid = threadIdx.x;
    const float* h = g_H[0] + (size_t)b * R_;
    float acc[O_];
#pragma unroll
    for (int o = 0; o < O_; o++) acc[o] = 0.f;
    for (int r = tid; r < R_; r += 256) {
        float hv = h[r];
#pragma unroll
        for (int o = 0; o < O_; o++) acc[o] += hv * W_out[r * O_ + o];
    }
#pragma unroll
    for (int o = 0; o < O_; o++)
#pragma unroll
        for (int off = 16; off > 0; off >>= 1)
            acc[o] += __shfl_down_sync(0xffffffffu, acc[o], off);
    __shared__ float s[8][O_];
    if ((tid & 31) == 0)
#pragma unroll
        for (int o = 0; o < O_; o++) s[tid >> 5][o] = acc[o];
    __syncthreads();
    if (tid < O_) {
        float v = b_out[tid];
#pragma unroll
        for (int w = 0; w < 8; w++) v += s[w][tid];
        out[b * O_ + tid] = v;
    }
}

extern "C" void kernel_launch(void* const* d_in, const int* in_sizes, int n_in,
                              void* d_out, int out_size)
{
    const float* x     = (const float*)d_in[0];
    const float* W_in  = (const float*)d_in[1];
    const float* W_res = (const float*)d_in[2];
    const float* W_out = (const float*)d_in[3];
    const float* b_out = (const float*)d_in[4];
    float* out = (float*)d_out;

    cudaFuncSetAttribute(esn_steps, cudaFuncAttributeMaxDynamicSharedMemorySize, SMEM_BYTES);

    prep_W<<<(1056 * 2048) / 256, 256>>>(W_res, W_in);
    prep_X<<<(B_ * T_ * 32) / 256, 256>>>(x);
    esn_zero<<<512, 256>>>();

    dim3 grid(32, 4);   // 128 CTAs, 1/SM, all co-resident -> dataflow flags safe
    esn_steps<<<grid, 384, SMEM_BYTES>>>();

    esn_readout<<<B_, 256>>>(W_out, b_out, out);
}

// round 15
// speedup vs baseline: 1.9096x; 1.6770x over previous
#include <cuda_runtime.h>
#include <cuda_fp16.h>
#include <cstdint>

#define B_ 256
#define T_ 512
#define R_ 2048
#define O_ 10

#define ACH_B 2048                 // bytes: one 32m x 32k A chunk (fragment order)
#define BCH_B 4096                 // bytes: one 32k x 64n B chunk (fragment order)
#define STAGE_B (ACH_B + BCH_B)    // 6 KB
#define NGROUP 6
#define SMEM_BYTES (3*NGROUP*STAGE_B)   // 3 stages x 6 groups = 108 KB

// ---------------- device scratch ----------------
__device__ __align__(128) float    g_H[2][B_ * R_];              // fp32 state (ping-pong)
__device__ __align__(128) uint32_t g_Hh[2][8 * 64 * 512];        // fp16 A chunks [mt][kt]
__device__ __align__(128) uint32_t g_Xh[T_ * 8 * 2 * 512];       // fp16 x chunks [t][mt][kc2]
__device__ __align__(128) uint32_t g_Wh[32 * 66 * 1024];         // fp16 B chunks [bn][kt]

__device__ __forceinline__ void cp16(void* dst, const void* src) {
    uint32_t d = (uint32_t)__cvta_generic_to_shared(dst);
    asm volatile("cp.async.cg.shared.global [%0], [%1], 16;\n" :: "r"(d), "l"(src));
}
__device__ __forceinline__ float tanh_fast(float x) {
    float r; asm("tanh.approx.f32 %0, %1;" : "=f"(r) : "f"(x)); return r;
}

#define MMA(cc, av, bb0, bb1) \
    asm volatile("mma.sync.aligned.m16n8k16.row.col.f32.f16.f16.f32 " \
        "{%0,%1,%2,%3},{%4,%5,%6,%7},{%8,%9},{%0,%1,%2,%3};\n" \
        : "+f"((cc)[0]), "+f"((cc)[1]), "+f"((cc)[2]), "+f"((cc)[3]) \
        : "r"((av).x), "r"((av).y), "r"((av).z), "r"((av).w), "r"(bb0), "r"(bb1))

// ---------------- prep: permute + fp16-round operands once ----------------
// A chunk (32m x 32k), u32 idx = ((kl*2 + q)*32 + lane)*4 + (rhi + 2*khalf)
//   m = q*16 + rhi*8 + g, k = kl*16 + khalf*8 + tg*2 + kodd, lane = g*4+tg, halves by kodd
// B chunk (32k x 64n), u32 idx = ((kl*4 + u)*32 + lane)*4 + (nio*2 + khalf)
//   n = u*16 + nio*8 + g, k as above
__global__ void prep_W(const float* __restrict__ Wres, const float* __restrict__ Win) {
    uint32_t idx = blockIdx.x * 256u + threadIdx.x;      // 1056*2048 k-pairs
    uint32_t k2 = idx >> 11, n = idx & 2047u;
    uint32_t k = k2 * 2u;
    float v0, v1;
    if (k < 2048u) { v0 = Wres[(size_t)k * R_ + n]; v1 = Wres[(size_t)(k + 1) * R_ + n]; }
    else           { v0 = Win[(size_t)(k - 2048u) * R_ + n]; v1 = Win[(size_t)(k - 2047u) * R_ + n]; }
    uint32_t kt = k >> 5, kk = k & 31u;
    uint32_t kl = kk >> 4, khalf = (kk >> 3) & 1u, tg = (kk & 7u) >> 1;
    uint32_t bn = n >> 6, nb = n & 63u, u = nb >> 4, nio = (nb >> 3) & 1u, g = nb & 7u;
    uint32_t lane = g * 4u + tg;
    __half2 h = __floats2half2_rn(v0, v1);
    g_Wh[(bn * 66u + kt) * 1024u + ((kl * 4u + u) * 32u + lane) * 4u + nio * 2u + khalf]
        = *(uint32_t*)&h;
}

__global__ void prep_X(const float* __restrict__ x) {
    uint32_t idx = blockIdx.x * 256u + threadIdx.x;      // 256*512*32 i-pairs
    uint32_t b = idx >> 14, t = (idx >> 5) & 511u, i = (idx & 31u) * 2u;
    float2 v = *(const float2*)(x + ((size_t)b * T_ + t) * 64u + i);
    uint32_t kc2 = i >> 5, kk = i & 31u;
    uint32_t kl = kk >> 4, khalf = (kk >> 3) & 1u, tg = (kk & 7u) >> 1;
    uint32_t mt = b >> 5, ml = b & 31u, q = ml >> 4, rhi = (ml >> 3) & 1u, g = ml & 7u;
    uint32_t lane = g * 4u + tg;
    __half2 h = __floats2half2_rn(v.x, v.y);
    g_Xh[((t * 8u + mt) * 2u + kc2) * 512u + ((kl * 2u + q) * 32u + lane) * 4u
         + rhi + 2u * khalf] = *(uint32_t*)&h;
}

__global__ void esn_zero() {
    uint32_t i = blockIdx.x * 256u + threadIdx.x;        // 131072
    ((float4*)g_H[0])[i] = make_float4(0.f, 0.f, 0.f, 0.f);
    if (i < 65536u) ((uint4*)g_Hh[0])[i] = make_uint4(0u, 0u, 0u, 0u);
}

// ---------------- step: H_new = 0.5H + 0.5 tanh([H|x_t] @ Wcat) ----------------
// CTA tile 32(M) x 64(N), grid (bn 0..31, mt 0..7) = 256 CTAs, 2 per SM.
// 192 threads = 6 single-warp split-K groups; group g: k32 tiles kt = 6j+g, j=0..10
// (kt 64,65 = x). Private 3-stage cp.async pipeline; no block barriers in mainloop.
__global__ __launch_bounds__(192, 2) void esn_step(int t)
{
    extern __shared__ char smem[];
    const int tid = threadIdx.x;
    const int gid = tid >> 5, lane = tid & 31;           // 6 groups = 6 warps
    const int bn = blockIdx.x, mt = blockIdx.y;
    const int cur = t & 1, nxt = cur ^ 1;
    char* gsm = smem + gid * 3 * STAGE_B;
    const int NCH = 11;

    __align__(16) float c[2][8][4];
#pragma unroll
    for (int q = 0; q < 2; q++)
#pragma unroll
        for (int no = 0; no < 8; no++)
#pragma unroll
            for (int i = 0; i < 4; i++) c[q][no][i] = 0.f;

    auto issue = [&](int j) {
        const int kt = 6 * j + gid;                      // k32 tile 0..65
        char* dst = gsm + (j % 3) * STAGE_B;
        const uint32_t* a = (kt < 64)
            ? (g_Hh[cur] + (size_t)(mt * 64 + kt) * 512)
            : (g_Xh + (size_t)((t * 8 + mt) * 2 + (kt - 64)) * 512);
        const uint32_t* b = g_Wh + (size_t)(bn * 66 + kt) * 1024;
#pragma unroll
        for (int it = 0; it < 4; it++) { int e = (it * 32 + lane) * 4; cp16(dst + e * 4, a + e); }
#pragma unroll
        for (int it = 0; it < 8; it++) { int e = (it * 32 + lane) * 4; cp16(dst + ACH_B + e * 4, b + e); }
        asm volatile("cp.async.commit_group;\n" ::);
    };

    issue(0); issue(1);

    for (int j = 0; j < NCH; j++) {
        if (j < NCH - 1) asm volatile("cp.async.wait_group 1;\n" ::);
        else             asm volatile("cp.async.wait_group 0;\n" ::);
        __syncwarp();
        if (j + 2 < NCH) issue(j + 2);

        const uint4* sA = (const uint4*)(gsm + (j % 3) * STAGE_B);
        const uint4* sB = (const uint4*)(gsm + (j % 3) * STAGE_B + ACH_B);
#pragma unroll
        for (int kl = 0; kl < 2; kl++) {                 // two k16 per k32 tile
            uint4 fa0 = sA[(kl * 2 + 0) * 32 + lane];
            uint4 fa1 = sA[(kl * 2 + 1) * 32 + lane];
            uint4 fb0 = sB[(kl * 4 + 0) * 32 + lane];
            uint4 fb1 = sB[(kl * 4 + 1) * 32 + lane];
            uint4 fb2 = sB[(kl * 4 + 2) * 32 + lane];
            uint4 fb3 = sB[(kl * 4 + 3) * 32 + lane];
            MMA(c[0][0], fa0, fb0.x, fb0.y);  MMA(c[0][1], fa0, fb0.z, fb0.w);
            MMA(c[0][2], fa0, fb1.x, fb1.y);  MMA(c[0][3], fa0, fb1.z, fb1.w);
            MMA(c[0][4], fa0, fb2.x, fb2.y);  MMA(c[0][5], fa0, fb2.z, fb2.w);
            MMA(c[0][6], fa0, fb3.x, fb3.y);  MMA(c[0][7], fa0, fb3.z, fb3.w);
            MMA(c[1][0], fa1, fb0.x, fb0.y);  MMA(c[1][1], fa1, fb0.z, fb0.w);
            MMA(c[1][2], fa1, fb1.x, fb1.y);  MMA(c[1][3], fa1, fb1.z, fb1.w);
            MMA(c[1][4], fa1, fb2.x, fb2.y);  MMA(c[1][5], fa1, fb2.z, fb2.w);
            MMA(c[1][6], fa1, fb3.x, fb3.y);  MMA(c[1][7], fa1, fb3.z, fb3.w);
        }
    }

    // ---------------- combine 6 split-K partials + epilogue ----------------
    // part[f 0..15][gid 0..5][lane] float4 = 48 KB (reuses pipeline smem).
    __syncthreads();
    float4* part = (float4*)smem;
#pragma unroll
    for (int q = 0; q < 2; q++)
#pragma unroll
        for (int no = 0; no < 8; no++) {
            const int f = q * 8 + no;
            part[(f * 6 + gid) * 32 + lane] = *(const float4*)c[q][no];
        }
    __syncthreads();

    // 512 slots (f 0..15, ln 0..31) over 192 threads.
    for (int s = tid; s < 512; s += 192) {
        const int f = s >> 5, ln = s & 31;
        const int q = f >> 3, no = f & 7;
        const int g = ln >> 2, tg = ln & 3;
        const float4* p = part + (f * 6) * 32 + ln;
        float4 s0 = p[0 * 32], s1 = p[1 * 32], s2 = p[2 * 32];
        float4 s3 = p[3 * 32], s4 = p[4 * 32], s5 = p[5 * 32];
        float v[4];
        v[0] = ((s0.x + s1.x) + (s2.x + s3.x)) + (s4.x + s5.x);
        v[1] = ((s0.y + s1.y) + (s2.y + s3.y)) + (s4.y + s5.y);
        v[2] = ((s0.z + s1.z) + (s2.z + s3.z)) + (s4.z + s5.z);
        v[3] = ((s0.w + s1.w) + (s2.w + s3.w)) + (s4.w + s5.w);

        const int col = bn * 64 + no * 8 + tg * 2;
        const int kl = (no >> 1) & 1, khalf = no & 1;
        const uint32_t chunk = (uint32_t)(mt * 64 + bn * 2 + (no >> 2)) * 512u;
#pragma unroll
        for (int rhi = 0; rhi < 2; rhi++) {
            const int row = mt * 32 + q * 16 + rhi * 8 + g;
            const float2 ho = *(const float2*)(g_H[cur] + (size_t)row * R_ + col);
            float h0 = 0.5f * ho.x + 0.5f * tanh_fast(v[2 * rhi]);
            float h1 = 0.5f * ho.y + 0.5f * tanh_fast(v[2 * rhi + 1]);
            *(float2*)(g_H[nxt] + (size_t)row * R_ + col) = make_float2(h0, h1);
            __half2 hh = __floats2half2_rn(h0, h1);
            g_Hh[nxt][chunk + ((kl * 2 + q) * 32 + ln) * 4u + rhi + 2 * khalf]
                = *(uint32_t*)&hh;
        }
    }
}

// ---------------- readout ----------------
__global__ void esn_readout(const float* __restrict__ W_out,
                            const float* __restrict__ b_out,
                            float* __restrict__ out)
{
    int b = blockIdx.x, tid = threadIdx.x;
    const float* h = g_H[0] + (size_t)b * R_;
    float acc[O_];
#pragma unroll
    for (int o = 0; o < O_; o++) acc[o] = 0.f;
    for (int r = tid; r < R_; r += 256) {
        float hv = h[r];
#pragma unroll
        for (int o = 0; o < O_; o++) acc[o] += hv * W_out[r * O_ + o];
    }
#pragma unroll
    for (int o = 0; o < O_; o++)
#pragma unroll
        for (int off = 16; off > 0; off >>= 1)
            acc[o] += __shfl_down_sync(0xffffffffu, acc[o], off);
    __shared__ float s[8][O_];
    if ((tid & 31) == 0)
#pragma unroll
        for (int o = 0; o < O_; o++) s[tid >> 5][o] = acc[o];
    __syncthreads();
    if (tid < O_) {
        float v = b_out[tid];
#pragma unroll
        for (int w = 0; w < 8; w++) v += s[w][tid];
        out[b * O_ + tid] = v;
    }
}

extern "C" void kernel_launch(void* const* d_in, const int* in_sizes, int n_in,
                              void* d_out, int out_size)
{
    const float* x     = (const float*)d_in[0];
    const float* W_in  = (const float*)d_in[1];
    const float* W_res = (const float*)d_in[2];
    const float* W_out = (const float*)d_in[3];
    const float* b_out = (const float*)d_in[4];
    float* out = (float*)d_out;

    cudaFuncSetAttribute(esn_step, cudaFuncAttributeMaxDynamicSharedMemorySize, SMEM_BYTES);

    prep_W<<<(1056 * 2048) / 256, 256>>>(W_res, W_in);
    prep_X<<<(B_ * T_ * 32) / 256, 256>>>(x);
    esn_zero<<<512, 256>>>();

    dim3 grid(32, 8);   // bn x mt = 256 CTAs, 2 per SM
    for (int t = 0; t < T_; t++)
        esn_step<<<grid, 192, SMEM_BYTES>>>(t);

    esn_readout<<<B_, 256>>>(W_out, b_out, out);
}